// round 17
// baseline (speedup 1.0000x reference)
#include <cuda_runtime.h>
#include <cuda_fp16.h>
#include <mma.h>
#include <cstdint>

using namespace nvcuda;

#define NN 50000
#define NNP 50048  // padded row count (multiple of 128) for guard-free tile reads
#define NE 800000
#define NC 40

// ---------------- scratch (device globals, no alloc) ----------------
__device__ __align__(16) __half g_h3[(size_t)NN * 40];     // fp16 h for layer 3
__device__ __align__(16) __half g_hh[(size_t)NN * 128];    // fp16 h (GEMM out, agg gather)
__device__ __align__(16) __half g_act[(size_t)NNP * 128];  // fp16 activated output (padded)
__device__ __align__(16) __half g_wh[2 * 128 * 128];       // fp16 W1,W2 transposed [n][k]
__device__ float g_dinv[NN];
__device__ int   g_cnt[NN];
__device__ int   g_fill[NN];
__device__ int   g_rowptr[NN];    // block-local scan; + g_boff[blk] = global
__device__ int   g_srcs[NE];
__device__ int   g_bsum[64];
__device__ int   g_boff[64];

// ---------------- cp.async helpers ----------------
__device__ __forceinline__ void cp16(void* smem, const void* gmem) {
    uint32_t s = (uint32_t)__cvta_generic_to_shared(smem);
    asm volatile("cp.async.cg.shared.global [%0], [%1], 16;" :: "r"(s), "l"(gmem));
}
__device__ __forceinline__ void cp_commit_wait() {
    asm volatile("cp.async.commit_group;");
    asm volatile("cp.async.wait_group 0;");
}

// ---------------- weight conversion: g_wh[n][k] = fp16(W[k][n]) ----------------
__global__ void k_wtoh(const float* __restrict__ W1, const float* __restrict__ W2) {
    int i = blockIdx.x * blockDim.x + threadIdx.x;  // over 2*16384
    if (i < 16384) {
        int k = i >> 7, n = i & 127;
        g_wh[n * 128 + k] = __float2half(W1[i]);
    } else if (i < 32768) {
        int j = i - 16384;
        int k = j >> 7, n = j & 127;
        g_wh[16384 + n * 128 + k] = __float2half(W2[j]);
    }
}

// ---------------- degree / CSR build ----------------
__global__ void k_zcnt() {
    int i = blockIdx.x * blockDim.x + threadIdx.x;
    if (i < NN) { g_cnt[i] = 0; g_fill[i] = 0; }
}

__global__ void k_count(const int* __restrict__ dst) {
    int e = blockIdx.x * blockDim.x + threadIdx.x;
    if (e < NE) atomicAdd(&g_cnt[dst[e]], 1);
}

__global__ void k_scan1() {
    int i = blockIdx.x * 1024 + threadIdx.x;
    int v = (i < NN) ? g_cnt[i] : 0;
    if (i < NN) g_dinv[i] = rsqrtf((float)(v + 1));
    int lane = threadIdx.x & 31, wid = threadIdx.x >> 5;
    int x = v;
#pragma unroll
    for (int o = 1; o < 32; o <<= 1) {
        int y = __shfl_up_sync(0xffffffffu, x, o);
        if (lane >= o) x += y;
    }
    __shared__ int ws[32];
    if (lane == 31) ws[wid] = x;
    __syncthreads();
    if (wid == 0) {
        int s = ws[lane];
#pragma unroll
        for (int o = 1; o < 32; o <<= 1) {
            int y = __shfl_up_sync(0xffffffffu, s, o);
            if (lane >= o) s += y;
        }
        ws[lane] = s;
    }
    __syncthreads();
    int incl = x + (wid ? ws[wid - 1] : 0);
    if (i < NN) g_rowptr[i] = incl - v;
    if (threadIdx.x == 1023) g_bsum[blockIdx.x] = incl;
}

__global__ void k_scan2(int nb) {
    int lane = threadIdx.x;
    int a = (lane < nb) ? g_bsum[lane] : 0;
    int b = (lane + 32 < nb) ? g_bsum[lane + 32] : 0;
    int va = a, vb = b;
#pragma unroll
    for (int o = 1; o < 32; o <<= 1) {
        int y = __shfl_up_sync(0xffffffffu, a, o);
        if (lane >= o) a += y;
    }
    int tot = __shfl_sync(0xffffffffu, a, 31);
#pragma unroll
    for (int o = 1; o < 32; o <<= 1) {
        int y = __shfl_up_sync(0xffffffffu, b, o);
        if (lane >= o) b += y;
    }
    b += tot;
    if (lane < nb) g_boff[lane] = a - va;
    if (lane + 32 < nb) g_boff[lane + 32] = b - vb;
}

__global__ void k_scatter(const int* __restrict__ src, const int* __restrict__ dst) {
    int e = blockIdx.x * blockDim.x + threadIdx.x;
    if (e >= NE) return;
    int d = dst[e];
    int pos = g_rowptr[d] + g_boff[d >> 10] + atomicAdd(&g_fill[d], 1);
    g_srcs[pos] = src[e];
}

// ---------------- wmma tensor-core GEMM: g_hh = fp16(X @ W), 128x128 tile ------------
// Device-global operands bound INSIDE device code. LAYER 1: X = fp32 arg (convert).
// LAYER 2: X = g_act (fp16, padded -> guard-free cp.async copy).
#define XS_LD 144  // halves per smem row: 288B pitch (32B-aligned rows, ldm % 8 == 0)
template <int LAYER>
__global__ __launch_bounds__(256) void k_gemmW(const float* __restrict__ xext) {
    extern __shared__ __half sh[];
    __half* sX = sh;                  // [128][XS_LD] row-major (m, k)
    __half* sW = sh + 128 * XS_LD;    // [128][XS_LD] n-major, k contiguous == col-major B
    const int tid = threadIdx.x;
    const int warp = tid >> 5, lane = tid & 31;
    const int r0 = blockIdx.x * 128;

    const __half* __restrict__ Wt = (LAYER == 1) ? g_wh : (g_wh + 16384);

    // W tile: pure cp.async copy
    for (int i = tid; i < 128 * 16; i += 256) {
        int n = i >> 4, cq = i & 15;
        cp16(sW + n * XS_LD + cq * 8, Wt + (size_t)n * 128 + cq * 8);
    }
    // X tile
    if (LAYER == 2) {
        // fp16 source, padded to NNP rows: guard-free cp.async copy
        for (int i = tid; i < 128 * 16; i += 256) {
            int row = i >> 4, cq = i & 15;
            cp16(sX + row * XS_LD + cq * 8, g_act + (size_t)(r0 + row) * 128 + cq * 8);
        }
    } else {
        // fp32 source: convert through registers
        for (int i = tid; i < 128 * 16; i += 256) {
            int row = i >> 4, cq = i & 15;
            int grow = r0 + row;
            uint4 v = make_uint4(0u, 0u, 0u, 0u);
            if (grow < NN) {
                const float4* fp = (const float4*)(xext + (size_t)grow * 128);
                float4 f0 = fp[2 * cq], f1 = fp[2 * cq + 1];
                __half2 h0 = __floats2half2_rn(f0.x, f0.y);
                __half2 h1 = __floats2half2_rn(f0.z, f0.w);
                __half2 h2 = __floats2half2_rn(f1.x, f1.y);
                __half2 h3 = __floats2half2_rn(f1.z, f1.w);
                v.x = *reinterpret_cast<unsigned*>(&h0);
                v.y = *reinterpret_cast<unsigned*>(&h1);
                v.z = *reinterpret_cast<unsigned*>(&h2);
                v.w = *reinterpret_cast<unsigned*>(&h3);
            }
            *(uint4*)(sX + row * XS_LD + cq * 8) = v;
        }
    }
    cp_commit_wait();
    __syncthreads();

    wmma::fragment<wmma::accumulator, 16, 16, 16, float> cf[8];
#pragma unroll
    for (int p = 0; p < 8; p++) wmma::fill_fragment(cf[p], 0.0f);

    const int mrow = warp * 16;
#pragma unroll
    for (int kk = 0; kk < 128; kk += 16) {
        wmma::fragment<wmma::matrix_a, 16, 16, 16, __half, wmma::row_major> af;
        wmma::load_matrix_sync(af, sX + mrow * XS_LD + kk, XS_LD);
#pragma unroll
        for (int p = 0; p < 8; p++) {
            wmma::fragment<wmma::matrix_b, 16, 16, 16, __half, wmma::col_major> bf;
            wmma::load_matrix_sync(bf, sW + (p * 16) * XS_LD + kk, XS_LD);
            wmma::mma_sync(cf[p], af, bf, cf[p]);
        }
    }

    // epilogue: stage fp32 per-warp strip in (reused) smem, convert, coalesced stores
    __syncthreads();
    float* outs = (float*)sh + warp * 16 * 128;  // 8KB per warp
#pragma unroll
    for (int p = 0; p < 8; p++)
        wmma::store_matrix_sync(outs + p * 16, cf[p], 128, wmma::mem_row_major);
    __syncwarp();
#pragma unroll
    for (int r = 0; r < 16; r++) {
        int row = r0 + mrow + r;
        if (row < NN) {
            float4 v = *(float4*)&outs[r * 128 + lane * 4];
            __half2 p0 = __floats2half2_rn(v.x, v.y);
            __half2 p1 = __floats2half2_rn(v.z, v.w);
            uint2 pk;
            pk.x = *reinterpret_cast<unsigned*>(&p0);
            pk.y = *reinterpret_cast<unsigned*>(&p1);
            *(uint2*)&g_hh[(size_t)row * 128 + lane * 4] = pk;
        }
    }
}

// ---------------- GEMM 128->40 (layer 3): fp16 act in, fp16 h3 out ----------------
__global__ void k_gemm3(const float* __restrict__ W) {
    constexpr int K2 = 64, OUTTOT = 40, OUTB = 40, COLT = 20, R = 16;
    __shared__ float2 Wp[K2][OUTB];
    __shared__ float2 xs[R][K2];
    const int tid = threadIdx.x;
    const int nthr = COLT * 4;  // 80
    const int r0 = blockIdx.x * R;

    for (int idx = tid; idx < K2 * OUTB; idx += nthr) {
        int k2 = idx / OUTB, t = idx % OUTB;
        Wp[k2][t] = make_float2(W[(size_t)(2 * k2) * OUTTOT + t],
                                W[(size_t)(2 * k2 + 1) * OUTTOT + t]);
    }
    const __half2* X2 = (const __half2*)g_act;
    for (int idx = tid; idx < R * K2; idx += nthr) {
        int r = idx / K2, k2 = idx % K2;
        int row = r0 + r;
        xs[r][k2] = (row < NN) ? __half22float2(X2[(size_t)row * K2 + k2])
                               : make_float2(0.f, 0.f);
    }
    __syncthreads();

    const int cx = tid % COLT;
    const int ry = tid / COLT;
    const int rb = ry * 4;
    float a00[4], a01[4], a10[4], a11[4];
#pragma unroll
    for (int rr = 0; rr < 4; rr++) { a00[rr] = a01[rr] = a10[rr] = a11[rr] = 0.0f; }

#pragma unroll 8
    for (int k2 = 0; k2 < K2; k2++) {
        float4 w4 = *(const float4*)&Wp[k2][2 * cx];
#pragma unroll
        for (int rr = 0; rr < 4; rr++) {
            float2 xv = xs[rb + rr][k2];
            a00[rr] = fmaf(xv.x, w4.x, a00[rr]);
            a01[rr] = fmaf(xv.y, w4.y, a01[rr]);
            a10[rr] = fmaf(xv.x, w4.z, a10[rr]);
            a11[rr] = fmaf(xv.y, w4.w, a11[rr]);
        }
    }

    const int c0 = 2 * cx;
#pragma unroll
    for (int rr = 0; rr < 4; rr++) {
        int row = r0 + rb + rr;
        if (row < NN) {
            __half2 hp = __floats2half2_rn(a00[rr] + a01[rr], a10[rr] + a11[rr]);
            *(__half2*)&g_h3[(size_t)row * OUTTOT + c0] = hp;
        }
    }
}

// ---------------- fused aggregation (warp per node), fp16 gather, fp16 act out -------
__global__ void k_agg128(const float* __restrict__ bias) {
    const int gid = blockIdx.x * blockDim.x + threadIdx.x;
    const int v = gid >> 5;
    if (v >= NN) return;
    const int lane = gid & 31;
    const float di = g_dinv[v];

    uint2 rs = *(const uint2*)(g_hh + (size_t)v * 128 + 4 * lane);
    float2 f0 = __half22float2(*reinterpret_cast<__half2*>(&rs.x));
    float2 f1 = __half22float2(*reinterpret_cast<__half2*>(&rs.y));
    float4 acc = make_float4(di * f0.x, di * f0.y, di * f1.x, di * f1.y);

    const int n = g_cnt[v];
    const int* __restrict__ sp = g_srcs + g_rowptr[v] + g_boff[v >> 10];
    int j = 0;
    for (; j + 4 <= n; j += 4) {
        int s1 = sp[j], s2 = sp[j + 1], s3 = sp[j + 2], s4 = sp[j + 3];
        float d1 = g_dinv[s1], d2 = g_dinv[s2], d3 = g_dinv[s3], d4 = g_dinv[s4];
        uint2 r1 = *(const uint2*)(g_hh + (size_t)s1 * 128 + 4 * lane);
        uint2 r2 = *(const uint2*)(g_hh + (size_t)s2 * 128 + 4 * lane);
        uint2 r3 = *(const uint2*)(g_hh + (size_t)s3 * 128 + 4 * lane);
        uint2 r4 = *(const uint2*)(g_hh + (size_t)s4 * 128 + 4 * lane);
        float2 a1 = __half22float2(*reinterpret_cast<__half2*>(&r1.x));
        float2 b1 = __half22float2(*reinterpret_cast<__half2*>(&r1.y));
        float2 a2 = __half22float2(*reinterpret_cast<__half2*>(&r2.x));
        float2 b2 = __half22float2(*reinterpret_cast<__half2*>(&r2.y));
        float2 a3 = __half22float2(*reinterpret_cast<__half2*>(&r3.x));
        float2 b3 = __half22float2(*reinterpret_cast<__half2*>(&r3.y));
        float2 a4 = __half22float2(*reinterpret_cast<__half2*>(&r4.x));
        float2 b4 = __half22float2(*reinterpret_cast<__half2*>(&r4.y));
        acc.x += d1 * a1.x + d2 * a2.x + d3 * a3.x + d4 * a4.x;
        acc.y += d1 * a1.y + d2 * a2.y + d3 * a3.y + d4 * a4.y;
        acc.z += d1 * b1.x + d2 * b2.x + d3 * b3.x + d4 * b4.x;
        acc.w += d1 * b1.y + d2 * b2.y + d3 * b3.y + d4 * b4.y;
    }
    for (; j < n; j++) {
        int s = sp[j];
        float ds = g_dinv[s];
        uint2 r = *(const uint2*)(g_hh + (size_t)s * 128 + 4 * lane);
        float2 a = __half22float2(*reinterpret_cast<__half2*>(&r.x));
        float2 b = __half22float2(*reinterpret_cast<__half2*>(&r.y));
        acc.x += ds * a.x; acc.y += ds * a.y; acc.z += ds * b.x; acc.w += ds * b.y;
    }
    const float4 bb = ((const float4*)bias)[lane];
    float ox = fmaxf(fmaf(di, acc.x, bb.x), 0.f);
    float oy = fmaxf(fmaf(di, acc.y, bb.y), 0.f);
    float oz = fmaxf(fmaf(di, acc.z, bb.z), 0.f);
    float ow = fmaxf(fmaf(di, acc.w, bb.w), 0.f);
    __half2 p0 = __floats2half2_rn(ox, oy);
    __half2 p1 = __floats2half2_rn(oz, ow);
    uint2 pk;
    pk.x = *reinterpret_cast<unsigned*>(&p0);
    pk.y = *reinterpret_cast<unsigned*>(&p1);
    ((uint2*)g_act)[(size_t)v * 32 + lane] = pk;
}

// ---------------- fused layer-3 aggregation + bias + log_softmax ----------------
__global__ void k_agg40(const float* __restrict__ bias, float* __restrict__ out) {
    const int gid = blockIdx.x * blockDim.x + threadIdx.x;
    const int v = gid >> 5;
    if (v >= NN) return;
    const int lane = gid & 31;
    const bool act = lane < 10;  // 40 halves = 10 x uint2(4 halves)
    const float di = g_dinv[v];
    float4 acc = make_float4(0.f, 0.f, 0.f, 0.f);
    if (act) {
        uint2 hv = *(const uint2*)(g_h3 + (size_t)v * 40 + 4 * lane);
        float2 a = __half22float2(*reinterpret_cast<__half2*>(&hv.x));
        float2 b = __half22float2(*reinterpret_cast<__half2*>(&hv.y));
        acc = make_float4(di * a.x, di * a.y, di * b.x, di * b.y);
    }
    const int n = g_cnt[v];
    const int* __restrict__ sp = g_srcs + g_rowptr[v] + g_boff[v >> 10];
    int j = 0;
    for (; j + 2 <= n; j += 2) {
        int s1 = sp[j], s2 = sp[j + 1];
        float d1 = g_dinv[s1], d2 = g_dinv[s2];
        if (act) {
            uint2 r1 = *(const uint2*)(g_h3 + (size_t)s1 * 40 + 4 * lane);
            uint2 r2 = *(const uint2*)(g_h3 + (size_t)s2 * 40 + 4 * lane);
            float2 a1 = __half22float2(*reinterpret_cast<__half2*>(&r1.x));
            float2 b1 = __half22float2(*reinterpret_cast<__half2*>(&r1.y));
            float2 a2 = __half22float2(*reinterpret_cast<__half2*>(&r2.x));
            float2 b2 = __half22float2(*reinterpret_cast<__half2*>(&r2.y));
            acc.x += d1 * a1.x + d2 * a2.x;
            acc.y += d1 * a1.y + d2 * a2.y;
            acc.z += d1 * b1.x + d2 * b2.x;
            acc.w += d1 * b1.y + d2 * b2.y;
        }
    }
    if (j < n) {
        int s = sp[j];
        float ds = g_dinv[s];
        if (act) {
            uint2 r = *(const uint2*)(g_h3 + (size_t)s * 40 + 4 * lane);
            float2 a = __half22float2(*reinterpret_cast<__half2*>(&r.x));
            float2 b = __half22float2(*reinterpret_cast<__half2*>(&r.y));
            acc.x += ds * a.x; acc.y += ds * a.y; acc.z += ds * b.x; acc.w += ds * b.y;
        }
    }
    float4 z = make_float4(0.f, 0.f, 0.f, 0.f);
    if (act) {
        const float4 bb = ((const float4*)bias)[lane];
        z.x = fmaf(di, acc.x, bb.x);
        z.y = fmaf(di, acc.y, bb.y);
        z.z = fmaf(di, acc.z, bb.z);
        z.w = fmaf(di, acc.w, bb.w);
    }
    float m = act ? fmaxf(fmaxf(z.x, z.y), fmaxf(z.z, z.w)) : -1e30f;
#pragma unroll
    for (int o = 16; o >= 1; o >>= 1) m = fmaxf(m, __shfl_xor_sync(0xffffffffu, m, o));
    float s = act ? (expf(z.x - m) + expf(z.y - m) + expf(z.z - m) + expf(z.w - m)) : 0.f;
#pragma unroll
    for (int o = 16; o >= 1; o >>= 1) s += __shfl_xor_sync(0xffffffffu, s, o);
    const float lse = m + logf(s);
    if (act) {
        ((float4*)out)[v * 10 + lane] =
            make_float4(z.x - lse, z.y - lse, z.z - lse, z.w - lse);
    }
}

// ---------------- launch ----------------
extern "C" void kernel_launch(void* const* d_in, const int* in_sizes, int n_in,
                              void* d_out, int out_size) {
    const float* x  = (const float*)d_in[0];
    const int* ei   = (const int*)d_in[1];
    const int* esrc = ei;
    const int* edst = ei + NE;
    const float* W1 = (const float*)d_in[2];
    const float* b1 = (const float*)d_in[3];
    const float* W2 = (const float*)d_in[4];
    const float* b2 = (const float*)d_in[5];
    const float* W3 = (const float*)d_in[6];
    const float* b3 = (const float*)d_in[7];
    float* out = (float*)d_out;

    const int TB = 256;
    const int nodeBlocks = (NN + TB - 1) / TB;
    const int edgeBlocks = (NE + TB - 1) / TB;
    const int warpBlocks = (NN * 32 + TB - 1) / TB;
    const int scanBlocks = (NN + 1023) / 1024;        // 49
    const int gemmRows = (NN + 127) / 128;            // 391
    const int gemm3Rows = (NN + 15) / 16;             // 3125
    const int gemmSmem = 2 * 128 * XS_LD * 2;         // 73728 B

    static bool init = false;
    static cudaStream_t sB;
    static cudaEvent_t evF, evJ;
    if (!init) {
        cudaFuncSetAttribute(k_gemmW<1>, cudaFuncAttributeMaxDynamicSharedMemorySize,
                             gemmSmem);
        cudaFuncSetAttribute(k_gemmW<2>, cudaFuncAttributeMaxDynamicSharedMemorySize,
                             gemmSmem);
        cudaStreamCreateWithFlags(&sB, cudaStreamNonBlocking);
        cudaEventCreateWithFlags(&evF, cudaEventDisableTiming);
        cudaEventCreateWithFlags(&evJ, cudaEventDisableTiming);
        init = true;
    }

    cudaEventRecord(evF, 0);
    cudaStreamWaitEvent(sB, evF, 0);

    k_wtoh<<<128, TB>>>(W1, W2);                            // 0 (main)
    k_zcnt<<<nodeBlocks, TB, 0, sB>>>();                    // 1 (sB)
    k_count<<<edgeBlocks, TB, 0, sB>>>(edst);               // 2 (sB)
    k_gemmW<1><<<gemmRows, 256, gemmSmem>>>(x);             // 3 (main) <- profiled
    k_scan1<<<scanBlocks, 1024, 0, sB>>>();                 // 4 (sB)
    k_scan2<<<1, 32, 0, sB>>>(scanBlocks);                  // 5 (sB)
    k_scatter<<<edgeBlocks, TB, 0, sB>>>(esrc, edst);       // 6 (sB)
    cudaEventRecord(evJ, sB);

    cudaStreamWaitEvent(0, evJ, 0);

    k_agg128<<<warpBlocks, TB>>>(b1);                       // 7
    k_gemmW<2><<<gemmRows, 256, gemmSmem>>>(nullptr);       // 8
    k_agg128<<<warpBlocks, TB>>>(b2);                       // 9
    k_gemm3<<<gemm3Rows, 80>>>(W3);                         // 10
    k_agg40<<<warpBlocks, TB>>>(b3, out);                   // 11
}